// round 2
// baseline (speedup 1.0000x reference)
#include <cuda_runtime.h>
#include <math.h>

#define BB 8
#define NN 64
#define HH 128
#define HEADS 4
#define HD 128
#define INNER 512
#define EE 8
#define NEdg 4032
#define LL 8
#define ROWS (BB*NN)   // 512
#define SPLITJ 4
#define JB (NN/SPLITJ) // 16

// ---------- persistent scratch (device globals; no allocations) ----------
__device__ float g_x[ROWS*HH];
__device__ float g_q[ROWS*INNER];
__device__ float g_k[ROWS*INNER];
__device__ float g_v[ROWS*INNER];
__device__ float g_skip[ROWS*HH];
__device__ float g_aggH[BB*HEADS*NN*HH];
__device__ float g_P[ROWS*EE];
__device__ float g_D[ROWS*EE];
__device__ int   g_eid[NN*NN];

// ---------- kernel 0: initial x = relu(noise@fc1 + b) broadcast; build eid LUT ----------
__global__ void k_init(const float* __restrict__ noise, const float* __restrict__ fc1_w,
                       const float* __restrict__ fc1_b, const int* __restrict__ eidx) {
    int b = blockIdx.x, t = threadIdx.x;  // 8 blocks x 128 threads
    float acc = fc1_b[t];
    #pragma unroll 4
    for (int i = 0; i < 128; i++) acc += noise[b*128 + i] * fc1_w[i*128 + t];
    acc = fmaxf(acc, 0.f);
    for (int n = 0; n < NN; n++) g_x[(b*NN + n)*HH + t] = acc;
    // each block fills 4032/8 = 504 edges of the LUT
    for (int e = b*504 + t; e < (b+1)*504; e += 128) {
        int s = eidx[e], d = eidx[NEdg + e];
        g_eid[s*NN + d] = e;
    }
}

// ---------- kernel A: fused Q/K/V/skip projections as one tiled GEMM ----------
// C[512, 1664] = x[512,128] @ [qw|kw|vw|sw], grid (26, 8), 256 threads, BM=BN=64, BK=16
__global__ void k_proj(int l,
                       const float* __restrict__ qw, const float* __restrict__ qb,
                       const float* __restrict__ kw, const float* __restrict__ kb,
                       const float* __restrict__ vw, const float* __restrict__ vb,
                       const float* __restrict__ sw, const float* __restrict__ sb) {
    __shared__ float As[16][68];
    __shared__ float Bs[16][64];
    int ct = blockIdx.x, rt = blockIdx.y;
    const float* W; const float* bias; int ld, coff; float* outp;
    if (ct < 8)       { W = qw + l*HH*INNER; bias = qb + l*INNER; ld = INNER; coff = ct*64;      outp = g_q;   }
    else if (ct < 16) { W = kw + l*HH*INNER; bias = kb + l*INNER; ld = INNER; coff = (ct-8)*64;  outp = g_k;   }
    else if (ct < 24) { W = vw + l*HH*INNER; bias = vb + l*INNER; ld = INNER; coff = (ct-16)*64; outp = g_v;   }
    else              { W = sw + l*HH*HH;    bias = sb + l*HH;    ld = HH;    coff = (ct-24)*64; outp = g_skip;}
    int t = threadIdx.x;
    int tx = t % 16, ty = t / 16;
    float c[4][4] = {};
    int r0 = rt*64;
    for (int k0 = 0; k0 < 128; k0 += 16) {
        {   // A tile: 64 rows x 16 k, each thread loads float4 along k
            int row = t >> 2, kq = (t & 3) << 2;
            float4 a4 = *(const float4*)&g_x[(r0+row)*HH + k0 + kq];
            As[kq+0][row] = a4.x; As[kq+1][row] = a4.y; As[kq+2][row] = a4.z; As[kq+3][row] = a4.w;
        }
        {   // B tile: 16 k x 64 cols
            int kk = t >> 4, n4 = (t & 15) << 2;
            float4 b4 = *(const float4*)&W[(k0+kk)*ld + coff + n4];
            Bs[kk][n4+0]=b4.x; Bs[kk][n4+1]=b4.y; Bs[kk][n4+2]=b4.z; Bs[kk][n4+3]=b4.w;
        }
        __syncthreads();
        #pragma unroll
        for (int kk = 0; kk < 16; kk++) {
            float a[4], bv[4];
            #pragma unroll
            for (int r = 0; r < 4; r++) a[r] = As[kk][ty*4+r];
            #pragma unroll
            for (int cc = 0; cc < 4; cc++) bv[cc] = Bs[kk][tx*4+cc];
            #pragma unroll
            for (int r = 0; r < 4; r++)
                #pragma unroll
                for (int cc = 0; cc < 4; cc++) c[r][cc] += a[r]*bv[cc];
        }
        __syncthreads();
    }
    #pragma unroll
    for (int r = 0; r < 4; r++)
        #pragma unroll
        for (int cc = 0; cc < 4; cc++) {
            int row = r0 + ty*4 + r, col = coff + tx*4 + cc;
            outp[row*ld + col] = c[r][cc] + bias[col];
        }
}

// ---------- kernel B: dense attention per (graph, head, dst-quarter) ----------
// grid = B*HEADS*SPLITJ = 128 blocks, 256 threads
__global__ void k_attn(int l, const float* __restrict__ edge_attr, const float* __restrict__ e_w) {
    __shared__ float sS[JB][68];
    __shared__ float sEw[EE][HD];
    __shared__ float sQE[JB][EE];
    __shared__ float sAE[JB][EE];
    __shared__ float sU[NN*HD];     // union: (Qc,Kc) chunks during scores; full V during agg
    int blk = blockIdx.x;
    int jseg = blk % SPLITJ;
    int h = (blk / SPLITJ) % HEADS;
    int b = blk / (SPLITJ*HEADS);
    int jbase = jseg * JB;
    int t = threadIdx.x;
    const float scale = 0.08838834764831845f; // 1/sqrt(128)

    for (int idx = t; idx < EE*HD; idx += 256)
        sEw[idx/HD][idx%HD] = e_w[((size_t)l*EE + idx/HD)*INNER + h*HD + idx%HD];

    // ---- scores: S[j,i] = q[j]·k[i], accumulated over 4 chunks of 32 dims ----
    int jg = t / 32;   // 8 groups -> 2 j each
    int ig = t % 32;   // 32 groups -> 2 i each
    float acc00 = 0.f, acc01 = 0.f, acc10 = 0.f, acc11 = 0.f;
    float qeacc = 0.f;   // thread t<128 owns qe[j=t/8][f=t%8]
    float* sQc = sU;            // [JB][32]
    float* sKc = sU + JB*32;    // [NN][32]
    for (int dc = 0; dc < 4; dc++) {
        int d0 = dc*32;
        __syncthreads();
        for (int idx = t; idx < JB*32; idx += 256)
            sQc[idx] = g_q[((b*NN + jbase + idx/32)*INNER) + h*HD + d0 + (idx & 31)];
        for (int idx = t; idx < NN*32; idx += 256)
            sKc[idx] = g_k[((b*NN + idx/32)*INNER) + h*HD + d0 + (idx & 31)];
        __syncthreads();
        #pragma unroll
        for (int dd = 0; dd < 32; dd++) {
            float q0 = sQc[(jg*2+0)*32+dd], q1 = sQc[(jg*2+1)*32+dd];
            float k0 = sKc[(ig*2+0)*32+dd], k1 = sKc[(ig*2+1)*32+dd];
            acc00 += q0*k0; acc01 += q0*k1; acc10 += q1*k0; acc11 += q1*k1;
        }
        if (t < JB*EE) {
            int jj = t / EE, f = t % EE;
            float s = 0.f;
            #pragma unroll
            for (int dd = 0; dd < 32; dd++) s += sQc[jj*32+dd] * sEw[f][d0+dd];
            qeacc += s;
        }
    }
    __syncthreads();
    if (t < JB*EE) sQE[t/EE][t%EE] = qeacc;
    __syncthreads();

    // ---- edge bias + scale + self mask; write S ----
    float accs[2][2] = {{acc00, acc01}, {acc10, acc11}};
    #pragma unroll
    for (int rr = 0; rr < 2; rr++)
        #pragma unroll
        for (int cc = 0; cc < 2; cc++) {
            int jl = jg*2 + rr;          // local dst
            int j = jbase + jl;          // global dst
            int i = ig*2 + cc;           // global src
            float sc;
            if (i == j) sc = -1e30f;
            else {
                int eix = g_eid[i*NN + j];
                const float* ea = edge_attr + ((size_t)b*NEdg + eix)*EE;
                float bsum = 0.f;
                #pragma unroll
                for (int f = 0; f < EE; f++) bsum += ea[f] * sQE[jl][f];
                sc = (accs[rr][cc] + bsum) * scale;
            }
            sS[jl][i] = sc;
        }
    __syncthreads();

    // ---- softmax per dst row (16 lanes per row) ----
    {
        int row = t / 16, lane = t % 16;
        float m = -1e30f;
        for (int i = lane; i < NN; i += 16) m = fmaxf(m, sS[row][i]);
        #pragma unroll
        for (int o = 1; o < 16; o <<= 1) m = fmaxf(m, __shfl_xor_sync(0xffffffffu, m, o));
        float sum = 0.f;
        for (int i = lane; i < NN; i += 16) { float e = __expf(sS[row][i]-m); sS[row][i] = e; sum += e; }
        #pragma unroll
        for (int o = 1; o < 16; o <<= 1) sum += __shfl_xor_sync(0xffffffffu, sum, o);
        float inv = 1.f / sum;
        for (int i = lane; i < NN; i += 16) sS[row][i] *= inv;
    }
    __syncthreads();

    // ---- aggE[j,f] = sum_i alpha[j,i] * edge_attr[i->j, f] ----
    {
        int row = t / 16, lane = t % 16;
        int j = jbase + row;
        float ae[EE] = {};
        for (int i = lane; i < NN; i += 16) {
            if (i == j) continue;
            float a = sS[row][i];
            const float* ea = edge_attr + ((size_t)b*NEdg + g_eid[i*NN + j])*EE;
            #pragma unroll
            for (int f = 0; f < EE; f++) ae[f] += a * ea[f];
        }
        #pragma unroll
        for (int f = 0; f < EE; f++)
            #pragma unroll
            for (int o = 1; o < 16; o <<= 1) ae[f] += __shfl_xor_sync(0xffffffffu, ae[f], o);
        if (lane == 0)
            #pragma unroll
            for (int f = 0; f < EE; f++) sAE[row][f] = ae[f];
    }
    __syncthreads();
    // ---- load full V for this head into sU ----
    for (int idx = t; idx < NN*HD; idx += 256)
        sU[idx] = g_v[((b*NN + idx/HD)*INNER) + h*HD + (idx & 127)];
    __syncthreads();

    // ---- agg[j,d] = alpha[j,:] @ V + aggE[j,:] @ eW ----
    {
        int jg2 = t / 32; int j0 = jg2*2;    // 8 groups x 2 local j
        int dg = t % 32;  int d0 = dg*4;
        float a0[4] = {}, a1[4] = {};
        #pragma unroll 4
        for (int i = 0; i < NN; i++) {
            float al0 = sS[j0][i], al1 = sS[j0+1][i];
            float4 v4 = *(float4*)&sU[i*HD + d0];
            a0[0] += al0*v4.x; a0[1] += al0*v4.y; a0[2] += al0*v4.z; a0[3] += al0*v4.w;
            a1[0] += al1*v4.x; a1[1] += al1*v4.y; a1[2] += al1*v4.z; a1[3] += al1*v4.w;
        }
        #pragma unroll
        for (int jj = 0; jj < 2; jj++) {
            float et[4] = {};
            #pragma unroll
            for (int f = 0; f < EE; f++) {
                float aev = sAE[j0+jj][f];
                #pragma unroll
                for (int k = 0; k < 4; k++) et[k] += aev * sEw[f][d0+k];
            }
            float* dst = &g_aggH[(((size_t)b*HEADS + h)*NN + jbase + j0 + jj)*HD + d0];
            float* acc = jj ? a1 : a0;
            #pragma unroll
            for (int k = 0; k < 4; k++) dst[k] = acc[k] + et[k];
        }
    }
}

// ---------- kernel C: x = relu(mean_h(agg) + skip) ----------
__global__ void k_combine() {   // grid 64, block 256
    int idx = blockIdx.x*1024 + threadIdx.x;
    for (int k = 0; k < 4; k++, idx += 256) {
        int row = idx / HH, d = idx & 127;
        int b = row / NN, n = row % NN;
        float s = 0.f;
        #pragma unroll
        for (int h = 0; h < HEADS; h++)
            s += g_aggH[(((size_t)b*HEADS + h)*NN + n)*HH + d];
        g_x[idx] = fmaxf(s*0.25f + g_skip[idx], 0.f);
    }
}

// ---------- kernel D: node head + P/D precompute for edge head ----------
__global__ void k_node(const float* __restrict__ atom_w, const float* __restrict__ atom_b,
                       const float* __restrict__ other_w, const float* __restrict__ other_b,
                       const float* __restrict__ efw, float* __restrict__ out) {
    __shared__ float xr[HH];
    __shared__ float outs[40];
    __shared__ float red[2];
    int node = blockIdx.x; int t = threadIdx.x;   // 512 blocks x 64 threads
    xr[t] = g_x[node*HH + t];
    xr[t+64] = g_x[node*HH + t + 64];
    __syncthreads();
    if (t < 40) {
        float acc;
        if (t < 9)       { acc = atom_b[t];       for (int d = 0; d < HH; d++) acc += xr[d]*atom_w[d*9 + t]; }
        else if (t < 24) { int c = t-9; acc = other_b[c]; for (int d = 0; d < HH; d++) acc += xr[d]*other_w[d*15 + c]; }
        else if (t < 32) { int f = t-24; acc = 0.f; for (int d = 0; d < HH; d++) acc += xr[d]*efw[d*EE + f]; }
        else             { int f = t-32; acc = 0.f; for (int d = 0; d < HH; d++) acc += xr[d]*efw[(128+d)*EE + f]; }
        outs[t] = acc;
    }
    __syncthreads();
    if (t == 0) {
        float m = -1e30f;
        for (int a = 0; a < 9; a++) m = fmaxf(m, outs[a]);
        float s = 0.f;
        for (int a = 0; a < 9; a++) s += __expf(outs[a]-m);
        red[0] = m; red[1] = s;
    }
    __syncthreads();
    if (t < 9) {
        float p = __expf(outs[t]-red[0]) / red[1];
        out[node*24 + t] = 1.f/(1.f + __expf(-p));
    } else if (t < 24) {
        float o = 1.f/(1.f + __expf(-outs[t]));
        out[node*24 + t] = 1.f/(1.f + __expf(-o));
    } else if (t < 32) {
        g_P[node*EE + (t-24)] = outs[t];
    } else if (t < 40) {
        g_D[node*EE + (t-32)] = outs[t];
    }
}

// ---------- kernel E: edge head = sigmoid(P[src] + D[dst] + b) ----------
__global__ void k_edge(const int* __restrict__ eidx, const float* __restrict__ efb,
                       float* __restrict__ out) {
    int eg = blockIdx.x*256 + threadIdx.x;    // 126 blocks -> 32256 exactly
    if (eg >= BB*NEdg) return;
    int b = eg / NEdg, e = eg % NEdg;
    int s = eidx[e], d = eidx[NEdg + e];
    const float* P = &g_P[(b*NN + s)*EE];
    const float* D = &g_D[(b*NN + d)*EE];
    float* o = out + (size_t)BB*NN*24 + (size_t)eg*EE;
    #pragma unroll
    for (int f = 0; f < EE; f++) {
        float v = P[f] + D[f] + efb[f];
        o[f] = 1.f/(1.f + __expf(-v));
    }
}

extern "C" void kernel_launch(void* const* d_in, const int* in_sizes, int n_in,
                              void* d_out, int out_size) {
    const float* noise     = (const float*)d_in[0];
    const float* edge_attr = (const float*)d_in[1];
    const int*   edge_index= (const int*)  d_in[2];
    const float* fc1_w     = (const float*)d_in[3];
    const float* fc1_b     = (const float*)d_in[4];
    const float* q_w       = (const float*)d_in[5];
    const float* q_b       = (const float*)d_in[6];
    const float* k_w       = (const float*)d_in[7];
    const float* k_b       = (const float*)d_in[8];
    const float* v_w       = (const float*)d_in[9];
    const float* v_b       = (const float*)d_in[10];
    const float* e_w       = (const float*)d_in[11];
    const float* skip_w    = (const float*)d_in[12];
    const float* skip_b    = (const float*)d_in[13];
    const float* atom_w    = (const float*)d_in[14];
    const float* atom_b    = (const float*)d_in[15];
    const float* other_w   = (const float*)d_in[16];
    const float* other_b   = (const float*)d_in[17];
    const float* efw       = (const float*)d_in[18];
    const float* efb       = (const float*)d_in[19];
    float* out = (float*)d_out;

    k_init<<<8, 128>>>(noise, fc1_w, fc1_b, edge_index);
    for (int l = 0; l < LL; l++) {
        k_proj<<<dim3(26, 8), 256>>>(l, q_w, q_b, k_w, k_b, v_w, v_b, skip_w, skip_b);
        k_attn<<<BB*HEADS*SPLITJ, 256>>>(l, edge_attr, e_w);
        k_combine<<<64, 256>>>();
    }
    k_node<<<ROWS, 64>>>(atom_w, atom_b, other_w, other_b, efw, out);
    k_edge<<<126, 256>>>(edge_index, efb, out);
}